// round 1
// baseline (speedup 1.0000x reference)
#include <cuda_runtime.h>
#include <math.h>

#define DD 256
#define TWO_D 512
#define NB 16
#define AL 1024
#define TL 512

// ---------------- scratch (no allocations allowed) ----------------
__device__ float g_art0[NB * AL * DD];
__device__ float g_art1[NB * AL * DD];
__device__ float g_tpl0[NB * TL * DD];
__device__ float g_tpl1[NB * TL * DD];
__device__ float g_a2[NB * AL];
__device__ float g_t2[NB * TL];
__device__ float g_rowmax[NB * AL];

// ---------------- embedding gather ----------------
__global__ void gather_kernel(const int* __restrict__ idx,
                              const float* __restrict__ emb,
                              float* __restrict__ out, int nrows)
{
    int t = blockIdx.x * blockDim.x + threadIdx.x;   // one float4 per thread
    int total = nrows * (DD / 4);
    if (t >= total) return;
    int row = t / (DD / 4);
    int c4  = t % (DD / 4);
    int w = idx[row];
    reinterpret_cast<float4*>(out)[(size_t)row * (DD / 4) + c4] =
        reinterpret_cast<const float4*>(emb)[(size_t)w * (DD / 4) + c4];
}

// ---------------- fused conv1d(K=3, dilated) + GLU + residual ----------------
// y[b,l,co] = sum_{k,ci} x[b, l+(k-1)*dil, ci] * w[k,ci,co] + bias[co]
// out = x + y[:, :256] * sigmoid(y[:, 256:])
// Tile: 64 positions x (64 a-cols + 64 g-cols), reduction 768 in chunks of 16.
__global__ __launch_bounds__(256) void conv_glu_kernel(
    const float* __restrict__ x, float* __restrict__ out,
    const float* __restrict__ w, const float* __restrict__ bias,
    int L, int dil)
{
    __shared__ float As[16][68];   // transposed: As[kk][m]
    __shared__ float Ba[16][68];   // Ba[kk][j]
    __shared__ float Bg[16][68];

    const int l0  = blockIdx.x * 64;
    const int co0 = blockIdx.y * 64;
    const int b   = blockIdx.z;
    const int tid = threadIdx.x;
    const int tx  = tid & 15;
    const int ty  = tid >> 4;

    const float* xb = x + (size_t)b * L * DD;

    float acc_a[4][4], acc_g[4][4];
#pragma unroll
    for (int i = 0; i < 4; i++)
#pragma unroll
        for (int j = 0; j < 4; j++) { acc_a[i][j] = 0.f; acc_g[i][j] = 0.f; }

    const int am  = tid >> 2;         // 0..63 (position within tile)
    const int akk = (tid & 3) * 4;    // 0,4,8,12
    const int bkk = tid >> 4;         // 0..15
    const int bj  = (tid & 15) * 4;   // 0..60

    for (int c = 0; c < 48; ++c) {
        const int k   = c >> 4;               // kernel tap 0..2
        const int ci0 = (c & 15) << 4;        // input-channel base

        // stage loads in registers
        const int p = l0 + am + (k - 1) * dil;
        float4 va = make_float4(0.f, 0.f, 0.f, 0.f);
        if (p >= 0 && p < L)
            va = *reinterpret_cast<const float4*>(&xb[(size_t)p * DD + ci0 + akk]);

        const float* wr = w + ((size_t)(k * DD + ci0 + bkk)) * TWO_D + co0 + bj;
        float4 vba = *reinterpret_cast<const float4*>(wr);
        float4 vbg = *reinterpret_cast<const float4*>(wr + DD);

        __syncthreads();
        As[akk + 0][am] = va.x; As[akk + 1][am] = va.y;
        As[akk + 2][am] = va.z; As[akk + 3][am] = va.w;
        *reinterpret_cast<float4*>(&Ba[bkk][bj]) = vba;
        *reinterpret_cast<float4*>(&Bg[bkk][bj]) = vbg;
        __syncthreads();

#pragma unroll
        for (int kk = 0; kk < 16; ++kk) {
            float4 a4 = *reinterpret_cast<const float4*>(&As[kk][ty * 4]);
            float4 p4 = *reinterpret_cast<const float4*>(&Ba[kk][tx * 4]);
            float4 q4 = *reinterpret_cast<const float4*>(&Bg[kk][tx * 4]);
            float av[4] = {a4.x, a4.y, a4.z, a4.w};
            float bv[4] = {p4.x, p4.y, p4.z, p4.w};
            float gv[4] = {q4.x, q4.y, q4.z, q4.w};
#pragma unroll
            for (int i = 0; i < 4; i++)
#pragma unroll
                for (int j = 0; j < 4; j++) {
                    acc_a[i][j] = fmaf(av[i], bv[j], acc_a[i][j]);
                    acc_g[i][j] = fmaf(av[i], gv[j], acc_g[i][j]);
                }
        }
    }

    // epilogue: bias, GLU, residual
#pragma unroll
    for (int i = 0; i < 4; i++) {
        int l = l0 + ty * 4 + i;
        float4 xv = *reinterpret_cast<const float4*>(&xb[(size_t)l * DD + co0 + tx * 4]);
        float xa[4] = {xv.x, xv.y, xv.z, xv.w};
        float o[4];
#pragma unroll
        for (int j = 0; j < 4; j++) {
            int co = co0 + tx * 4 + j;
            float aa = acc_a[i][j] + bias[co];
            float gg = acc_g[i][j] + bias[co + DD];
            o[j] = xa[j] + aa * (1.f / (1.f + expf(-gg)));
        }
        *reinterpret_cast<float4*>(&out[((size_t)b * L + l) * DD + co0 + tx * 4]) =
            make_float4(o[0], o[1], o[2], o[3]);
    }
}

// ---------------- row squared norms (one warp per row) ----------------
__global__ void norms_kernel(const float* __restrict__ x, float* __restrict__ out,
                             int nrows)
{
    int warp = (blockIdx.x * blockDim.x + threadIdx.x) >> 5;
    int lane = threadIdx.x & 31;
    if (warp >= nrows) return;
    const float* r = x + (size_t)warp * DD;
    float s = 0.f;
#pragma unroll
    for (int c = lane * 2; c < DD; c += 64) {
        float2 v = *reinterpret_cast<const float2*>(&r[c]);
        s += v.x * v.x + v.y * v.y;
    }
#pragma unroll
    for (int o = 16; o; o >>= 1) s += __shfl_xor_sync(0xffffffffu, s, o);
    if (lane == 0) out[warp] = s;
}

// ---------------- fused distance GEMM + exp + mask + row-max ----------------
__global__ __launch_bounds__(256) void rowmax_kernel(
    const float* __restrict__ art, const float* __restrict__ tpl,
    const float* __restrict__ a2, const float* __restrict__ t2,
    const float* __restrict__ amask, const float* __restrict__ tmask,
    float* __restrict__ rowmax)
{
    __shared__ float As[16][68];
    __shared__ float Bs[16][68];

    const int l0  = blockIdx.x * 64;
    const int b   = blockIdx.y;
    const int tid = threadIdx.x;
    const int tx  = tid & 15;
    const int ty  = tid >> 4;

    const float* ab = art + (size_t)b * AL * DD;
    const float* tb = tpl + (size_t)b * TL * DD;

    const int am  = tid >> 2;
    const int akk = (tid & 3) * 4;

    float rmax[4] = {0.f, 0.f, 0.f, 0.f};   // S >= 0 always

    for (int t0 = 0; t0 < TL; t0 += 64) {
        float acc[4][4];
#pragma unroll
        for (int i = 0; i < 4; i++)
#pragma unroll
            for (int j = 0; j < 4; j++) acc[i][j] = 0.f;

        for (int c = 0; c < 16; ++c) {
            int d0 = c * 16;
            float4 va = *reinterpret_cast<const float4*>(&ab[(size_t)(l0 + am) * DD + d0 + akk]);
            float4 vb = *reinterpret_cast<const float4*>(&tb[(size_t)(t0 + am) * DD + d0 + akk]);
            __syncthreads();
            As[akk + 0][am] = va.x; As[akk + 1][am] = va.y;
            As[akk + 2][am] = va.z; As[akk + 3][am] = va.w;
            Bs[akk + 0][am] = vb.x; Bs[akk + 1][am] = vb.y;
            Bs[akk + 2][am] = vb.z; Bs[akk + 3][am] = vb.w;
            __syncthreads();
#pragma unroll
            for (int kk = 0; kk < 16; ++kk) {
                float4 a4 = *reinterpret_cast<const float4*>(&As[kk][ty * 4]);
                float4 b4 = *reinterpret_cast<const float4*>(&Bs[kk][tx * 4]);
                float av[4] = {a4.x, a4.y, a4.z, a4.w};
                float bv[4] = {b4.x, b4.y, b4.z, b4.w};
#pragma unroll
                for (int i = 0; i < 4; i++)
#pragma unroll
                    for (int j = 0; j < 4; j++)
                        acc[i][j] = fmaf(av[i], bv[j], acc[i][j]);
            }
        }

#pragma unroll
        for (int i = 0; i < 4; i++) {
            int l = l0 + ty * 4 + i;
            float av2 = a2[b * AL + l];
#pragma unroll
            for (int j = 0; j < 4; j++) {
                int t = t0 + tx * 4 + j;
                float dist = av2 + t2[b * TL + t] - 2.f * acc[i][j];
                dist = fmaxf(dist, 0.f);
                float s = expf(-dist) * tmask[b * TL + t];
                rmax[i] = fmaxf(rmax[i], s);
            }
        }
    }

    // reduce across tx (16-lane groups within each warp)
#pragma unroll
    for (int i = 0; i < 4; i++) {
        float v = rmax[i];
#pragma unroll
        for (int o = 8; o; o >>= 1) v = fmaxf(v, __shfl_xor_sync(0xffffffffu, v, o));
        if (tx == 0) {
            int l = l0 + ty * 4 + i;
            rowmax[b * AL + l] = v * amask[b * AL + l];
        }
    }
}

// ---------------- top-10 (sorted desc) + 2-layer MLP ----------------
__global__ void final_kernel(const float* __restrict__ rowmax,
                             const float* __restrict__ ff1w, const float* __restrict__ ff1b,
                             const float* __restrict__ ff2w, const float* __restrict__ ff2b,
                             float* __restrict__ out)
{
    __shared__ float vals[AL];
    __shared__ float rv[256];
    __shared__ int   ri[256];
    __shared__ float topv[10];

    int b = blockIdx.x;
    int tid = threadIdx.x;
    for (int i = tid; i < AL; i += 256) vals[i] = rowmax[b * AL + i];
    __syncthreads();

    for (int it = 0; it < 10; ++it) {
        float bv = -1.f; int bi = 0;
        for (int i = tid; i < AL; i += 256) {
            float v = vals[i];
            if (v > bv) { bv = v; bi = i; }
        }
        rv[tid] = bv; ri[tid] = bi;
        __syncthreads();
        for (int s = 128; s; s >>= 1) {
            if (tid < s && rv[tid + s] > rv[tid]) { rv[tid] = rv[tid + s]; ri[tid] = ri[tid + s]; }
            __syncthreads();
        }
        if (tid == 0) { topv[it] = rv[0]; vals[ri[0]] = -2.f; }
        __syncthreads();
    }

    if (tid == 0) {
        float o = ff2b[0];
#pragma unroll
        for (int j = 0; j < 10; j++) {
            float h = ff1b[j];
#pragma unroll
            for (int i = 0; i < 10; i++) h += topv[i] * ff1w[i * 10 + j];
            h = fmaxf(h, 0.f);
            o += h * ff2w[j];
        }
        out[b] = o;
    }
}

// ---------------- launcher ----------------
extern "C" void kernel_launch(void* const* d_in, const int* in_sizes, int n_in,
                              void* d_out, int out_size)
{
    const int*   art_w = (const int*)d_in[0];
    const int*   tpl_w = (const int*)d_in[2];
    const float* amask = (const float*)d_in[4];
    const float* tmask = (const float*)d_in[5];
    const float* emb   = (const float*)d_in[6];
    const float* exp_w = (const float*)d_in[7];
    const float* exp_b = (const float*)d_in[8];
    const float* ref_w = (const float*)d_in[9];
    const float* ref_b = (const float*)d_in[10];
    const float* ff1w  = (const float*)d_in[11];
    const float* ff1b  = (const float*)d_in[12];
    const float* ff2w  = (const float*)d_in[13];
    const float* ff2b  = (const float*)d_in[14];
    float* out = (float*)d_out;

    float *art0, *art1, *tpl0, *tpl1, *a2, *t2, *rmax;
    cudaGetSymbolAddress((void**)&art0, g_art0);
    cudaGetSymbolAddress((void**)&art1, g_art1);
    cudaGetSymbolAddress((void**)&tpl0, g_tpl0);
    cudaGetSymbolAddress((void**)&tpl1, g_tpl1);
    cudaGetSymbolAddress((void**)&a2,   g_a2);
    cudaGetSymbolAddress((void**)&t2,   g_t2);
    cudaGetSymbolAddress((void**)&rmax, g_rowmax);

    // 1. embedding gathers
    {
        int total_a = NB * AL * (DD / 4);
        gather_kernel<<<(total_a + 255) / 256, 256>>>(art_w, emb, art0, NB * AL);
        int total_t = NB * TL * (DD / 4);
        gather_kernel<<<(total_t + 255) / 256, 256>>>(tpl_w, emb, tpl0, NB * TL);
    }

    // 2. 10 residual conv-GLU blocks (7 expand dilated + 3 refine)
    const int dils[10] = {1, 2, 4, 8, 16, 32, 32, 1, 1, 1};
    for (int i = 0; i < 10; ++i) {
        const float* w  = (i < 7) ? exp_w + (size_t)i * 3 * DD * TWO_D
                                  : ref_w + (size_t)(i - 7) * 3 * DD * TWO_D;
        const float* bb = (i < 7) ? exp_b + i * TWO_D
                                  : ref_b + (i - 7) * TWO_D;
        float* ain  = (i & 1) ? art1 : art0;
        float* aout = (i & 1) ? art0 : art1;
        float* tin  = (i & 1) ? tpl1 : tpl0;
        float* tout = (i & 1) ? tpl0 : tpl1;
        conv_glu_kernel<<<dim3(AL / 64, 4, NB), 256>>>(ain, aout, w, bb, AL, dils[i]);
        conv_glu_kernel<<<dim3(TL / 64, 4, NB), 256>>>(tin, tout, w, bb, TL, dils[i]);
    }
    // after 10 ping-pongs, results are back in *0 buffers

    // 3. squared norms
    norms_kernel<<<(NB * AL) / 8, 256>>>(art0, a2, NB * AL);
    norms_kernel<<<(NB * TL) / 8, 256>>>(tpl0, t2, NB * TL);

    // 4. fused distance + exp + mask + row-max
    rowmax_kernel<<<dim3(AL / 64, NB), 256>>>(art0, tpl0, a2, t2, amask, tmask, rmax);

    // 5. top-10 + MLP
    final_kernel<<<NB, 256>>>(rmax, ff1w, ff1b, ff2w, ff2b, out);
}

// round 2
// speedup vs baseline: 1.1905x; 1.1905x over previous
#include <cuda_runtime.h>
#include <math.h>

#define DD 256
#define TWO_D 512
#define NB 16
#define AL 1024
#define TL 512

// packed fp32x2 ops (sm_103a; ptxas won't auto-fuse — must be PTX)
#define FMA2(d, a, b, c) \
    asm("fma.rn.f32x2 %0, %1, %2, %3;" : "=l"(d) : "l"(a), "l"(b), "l"(c))
#define PACK2(d, x) \
    asm("mov.b64 %0, {%1, %1};" : "=l"(d) : "f"(x))
#define UNPACK2(lo, hi, v) \
    asm("mov.b64 {%0, %1}, %2;" : "=f"(lo), "=f"(hi) : "l"(v))

// ---------------- scratch (no allocations allowed) ----------------
__device__ float g_art0[NB * AL * DD];
__device__ float g_art1[NB * AL * DD];
__device__ float g_tpl0[NB * TL * DD];
__device__ float g_tpl1[NB * TL * DD];
__device__ float g_a2[NB * AL];
__device__ float g_t2[NB * TL];
__device__ float g_rowmax[NB * AL];

// ---------------- embedding gather ----------------
__global__ void gather_kernel(const int* __restrict__ idx,
                              const float* __restrict__ emb,
                              float* __restrict__ out, int nrows)
{
    int t = blockIdx.x * blockDim.x + threadIdx.x;
    int total = nrows * (DD / 4);
    if (t >= total) return;
    int row = t / (DD / 4);
    int c4  = t % (DD / 4);
    int w = idx[row];
    reinterpret_cast<float4*>(out)[(size_t)row * (DD / 4) + c4] =
        reinterpret_cast<const float4*>(emb)[(size_t)w * (DD / 4) + c4];
}

// ---------------- fused conv1d(K=3, dilated) + GLU + residual ----------------
// 64 positions x (64 a-cols + 64 g-cols), K=768 in 48 chunks of 16.
// Double-buffered smem, packed f32x2 FMA.
__global__ __launch_bounds__(256) void conv_glu_kernel(
    const float* __restrict__ x, float* __restrict__ out,
    const float* __restrict__ w, const float* __restrict__ bias,
    int L, int dil)
{
    __shared__ __align__(16) float As[2][16][68];
    __shared__ __align__(16) float Ba[2][16][68];
    __shared__ __align__(16) float Bg[2][16][68];

    const int l0  = blockIdx.x * 64;
    const int co0 = blockIdx.y * 64;
    const int b   = blockIdx.z;
    const int tid = threadIdx.x;
    const int tx  = tid & 15;
    const int ty  = tid >> 4;

    const float* xb = x + (size_t)b * L * DD;

    unsigned long long accA[4][2], accG[4][2];
#pragma unroll
    for (int i = 0; i < 4; i++)
#pragma unroll
        for (int j = 0; j < 2; j++) { accA[i][j] = 0ull; accG[i][j] = 0ull; }

    const int am  = tid >> 2;         // 0..63 position within tile
    const int akk = (tid & 3) * 4;    // 0,4,8,12
    const int bkk = tid >> 4;         // 0..15
    const int bj  = (tid & 15) * 4;   // 0..60

    float4 va, vba, vbg;

    // ---- prefetch chunk 0 ----
    {
        const int p = l0 + am - dil;  // k=0
        va = make_float4(0.f, 0.f, 0.f, 0.f);
        if (p >= 0 && p < L)
            va = *reinterpret_cast<const float4*>(&xb[(size_t)p * DD + akk]);
        const float* wr = w + ((size_t)bkk) * TWO_D + co0 + bj;
        vba = *reinterpret_cast<const float4*>(wr);
        vbg = *reinterpret_cast<const float4*>(wr + DD);
    }
    As[0][akk + 0][am] = va.x; As[0][akk + 1][am] = va.y;
    As[0][akk + 2][am] = va.z; As[0][akk + 3][am] = va.w;
    *reinterpret_cast<float4*>(&Ba[0][bkk][bj]) = vba;
    *reinterpret_cast<float4*>(&Bg[0][bkk][bj]) = vbg;
    __syncthreads();

    for (int c = 0; c < 48; ++c) {
        const int st = c & 1;

        // prefetch chunk c+1 into registers
        if (c < 47) {
            const int cn  = c + 1;
            const int k   = cn >> 4;
            const int ci0 = (cn & 15) << 4;
            const int p = l0 + am + (k - 1) * dil;
            va = make_float4(0.f, 0.f, 0.f, 0.f);
            if (p >= 0 && p < L)
                va = *reinterpret_cast<const float4*>(&xb[(size_t)p * DD + ci0 + akk]);
            const float* wr = w + ((size_t)(k * DD + ci0 + bkk)) * TWO_D + co0 + bj;
            vba = *reinterpret_cast<const float4*>(wr);
            vbg = *reinterpret_cast<const float4*>(wr + DD);
        }

        // compute current chunk
#pragma unroll
        for (int kk = 0; kk < 16; ++kk) {
            float4 a4 = *reinterpret_cast<const float4*>(&As[st][kk][ty * 4]);
            ulonglong2 b2a = *reinterpret_cast<const ulonglong2*>(&Ba[st][kk][tx * 4]);
            ulonglong2 b2g = *reinterpret_cast<const ulonglong2*>(&Bg[st][kk][tx * 4]);
            unsigned long long d;
#define ROWSTEP(i, ax)                                       \
            PACK2(d, ax);                                    \
            FMA2(accA[i][0], d, b2a.x, accA[i][0]);          \
            FMA2(accA[i][1], d, b2a.y, accA[i][1]);          \
            FMA2(accG[i][0], d, b2g.x, accG[i][0]);          \
            FMA2(accG[i][1], d, b2g.y, accG[i][1]);
            ROWSTEP(0, a4.x)
            ROWSTEP(1, a4.y)
            ROWSTEP(2, a4.z)
            ROWSTEP(3, a4.w)
#undef ROWSTEP
        }

        // stage chunk c+1 into the other buffer
        if (c < 47) {
            const int sn = st ^ 1;
            As[sn][akk + 0][am] = va.x; As[sn][akk + 1][am] = va.y;
            As[sn][akk + 2][am] = va.z; As[sn][akk + 3][am] = va.w;
            *reinterpret_cast<float4*>(&Ba[sn][bkk][bj]) = vba;
            *reinterpret_cast<float4*>(&Bg[sn][bkk][bj]) = vbg;
        }
        __syncthreads();
    }

    // epilogue: bias, GLU, residual
#pragma unroll
    for (int i = 0; i < 4; i++) {
        int l = l0 + ty * 4 + i;
        float4 xv = *reinterpret_cast<const float4*>(&xb[(size_t)l * DD + co0 + tx * 4]);
        float xa[4] = {xv.x, xv.y, xv.z, xv.w};
        float o[4];
#pragma unroll
        for (int jp = 0; jp < 2; jp++) {
            float a0, a1, g0, g1;
            UNPACK2(a0, a1, accA[i][jp]);
            UNPACK2(g0, g1, accG[i][jp]);
            int co = co0 + tx * 4 + jp * 2;
            float aa0 = a0 + bias[co];
            float aa1 = a1 + bias[co + 1];
            float gg0 = g0 + bias[co + DD];
            float gg1 = g1 + bias[co + DD + 1];
            o[jp * 2 + 0] = xa[jp * 2 + 0] + aa0 * (1.f / (1.f + expf(-gg0)));
            o[jp * 2 + 1] = xa[jp * 2 + 1] + aa1 * (1.f / (1.f + expf(-gg1)));
        }
        *reinterpret_cast<float4*>(&out[((size_t)b * L + l) * DD + co0 + tx * 4]) =
            make_float4(o[0], o[1], o[2], o[3]);
    }
}

// ---------------- row squared norms (one warp per row) ----------------
__global__ void norms_kernel(const float* __restrict__ x, float* __restrict__ out,
                             int nrows)
{
    int warp = (blockIdx.x * blockDim.x + threadIdx.x) >> 5;
    int lane = threadIdx.x & 31;
    if (warp >= nrows) return;
    const float* r = x + (size_t)warp * DD;
    float s = 0.f;
#pragma unroll
    for (int c = lane * 2; c < DD; c += 64) {
        float2 v = *reinterpret_cast<const float2*>(&r[c]);
        s += v.x * v.x + v.y * v.y;
    }
#pragma unroll
    for (int o = 16; o; o >>= 1) s += __shfl_xor_sync(0xffffffffu, s, o);
    if (lane == 0) out[warp] = s;
}

// ---------------- fused distance GEMM + exp + mask + row-max ----------------
__global__ __launch_bounds__(256) void rowmax_kernel(
    const float* __restrict__ art, const float* __restrict__ tpl,
    const float* __restrict__ a2, const float* __restrict__ t2,
    const float* __restrict__ amask, const float* __restrict__ tmask,
    float* __restrict__ rowmax)
{
    __shared__ __align__(16) float As[16][68];
    __shared__ __align__(16) float Bs[16][68];

    const int l0  = blockIdx.x * 64;
    const int b   = blockIdx.y;
    const int tid = threadIdx.x;
    const int tx  = tid & 15;
    const int ty  = tid >> 4;

    const float* ab = art + (size_t)b * AL * DD;
    const float* tb = tpl + (size_t)b * TL * DD;

    const int am  = tid >> 2;
    const int akk = (tid & 3) * 4;

    float rmax[4] = {0.f, 0.f, 0.f, 0.f};

    for (int t0 = 0; t0 < TL; t0 += 64) {
        float acc[4][4];
#pragma unroll
        for (int i = 0; i < 4; i++)
#pragma unroll
            for (int j = 0; j < 4; j++) acc[i][j] = 0.f;

        for (int c = 0; c < 16; ++c) {
            int d0 = c * 16;
            float4 va = *reinterpret_cast<const float4*>(&ab[(size_t)(l0 + am) * DD + d0 + akk]);
            float4 vb = *reinterpret_cast<const float4*>(&tb[(size_t)(t0 + am) * DD + d0 + akk]);
            __syncthreads();
            As[akk + 0][am] = va.x; As[akk + 1][am] = va.y;
            As[akk + 2][am] = va.z; As[akk + 3][am] = va.w;
            Bs[akk + 0][am] = vb.x; Bs[akk + 1][am] = vb.y;
            Bs[akk + 2][am] = vb.z; Bs[akk + 3][am] = vb.w;
            __syncthreads();
#pragma unroll
            for (int kk = 0; kk < 16; ++kk) {
                float4 a4 = *reinterpret_cast<const float4*>(&As[kk][ty * 4]);
                float4 b4 = *reinterpret_cast<const float4*>(&Bs[kk][tx * 4]);
                float av[4] = {a4.x, a4.y, a4.z, a4.w};
                float bv[4] = {b4.x, b4.y, b4.z, b4.w};
#pragma unroll
                for (int i = 0; i < 4; i++)
#pragma unroll
                    for (int j = 0; j < 4; j++)
                        acc[i][j] = fmaf(av[i], bv[j], acc[i][j]);
            }
        }

#pragma unroll
        for (int i = 0; i < 4; i++) {
            int l = l0 + ty * 4 + i;
            float av2 = a2[b * AL + l];
#pragma unroll
            for (int j = 0; j < 4; j++) {
                int t = t0 + tx * 4 + j;
                float dist = av2 + t2[b * TL + t] - 2.f * acc[i][j];
                dist = fmaxf(dist, 0.f);
                float s = expf(-dist) * tmask[b * TL + t];
                rmax[i] = fmaxf(rmax[i], s);
            }
        }
    }

#pragma unroll
    for (int i = 0; i < 4; i++) {
        float v = rmax[i];
#pragma unroll
        for (int o = 8; o; o >>= 1) v = fmaxf(v, __shfl_xor_sync(0xffffffffu, v, o));
        if (tx == 0) {
            int l = l0 + ty * 4 + i;
            rowmax[b * AL + l] = v * amask[b * AL + l];
        }
    }
}

// ---------------- top-10 (sorted desc) + 2-layer MLP ----------------
__global__ void final_kernel(const float* __restrict__ rowmax,
                             const float* __restrict__ ff1w, const float* __restrict__ ff1b,
                             const float* __restrict__ ff2w, const float* __restrict__ ff2b,
                             float* __restrict__ out)
{
    __shared__ float vals[AL];
    __shared__ float rv[256];
    __shared__ int   ri[256];
    __shared__ float topv[10];

    int b = blockIdx.x;
    int tid = threadIdx.x;
    for (int i = tid; i < AL; i += 256) vals[i] = rowmax[b * AL + i];
    __syncthreads();

    for (int it = 0; it < 10; ++it) {
        float bv = -1.f; int bi = 0;
        for (int i = tid; i < AL; i += 256) {
            float v = vals[i];
            if (v > bv) { bv = v; bi = i; }
        }
        rv[tid] = bv; ri[tid] = bi;
        __syncthreads();
        for (int s = 128; s; s >>= 1) {
            if (tid < s && rv[tid + s] > rv[tid]) { rv[tid] = rv[tid + s]; ri[tid] = ri[tid + s]; }
            __syncthreads();
        }
        if (tid == 0) { topv[it] = rv[0]; vals[ri[0]] = -2.f; }
        __syncthreads();
    }

    if (tid == 0) {
        float o = ff2b[0];
#pragma unroll
        for (int j = 0; j < 10; j++) {
            float h = ff1b[j];
#pragma unroll
            for (int i = 0; i < 10; i++) h += topv[i] * ff1w[i * 10 + j];
            h = fmaxf(h, 0.f);
            o += h * ff2w[j];
        }
        out[b] = o;
    }
}

// ---------------- launcher ----------------
extern "C" void kernel_launch(void* const* d_in, const int* in_sizes, int n_in,
                              void* d_out, int out_size)
{
    const int*   art_w = (const int*)d_in[0];
    const int*   tpl_w = (const int*)d_in[2];
    const float* amask = (const float*)d_in[4];
    const float* tmask = (const float*)d_in[5];
    const float* emb   = (const float*)d_in[6];
    const float* exp_w = (const float*)d_in[7];
    const float* exp_b = (const float*)d_in[8];
    const float* ref_w = (const float*)d_in[9];
    const float* ref_b = (const float*)d_in[10];
    const float* ff1w  = (const float*)d_in[11];
    const float* ff1b  = (const float*)d_in[12];
    const float* ff2w  = (const float*)d_in[13];
    const float* ff2b  = (const float*)d_in[14];
    float* out = (float*)d_out;

    float *art0, *art1, *tpl0, *tpl1, *a2, *t2, *rmax;
    cudaGetSymbolAddress((void**)&art0, g_art0);
    cudaGetSymbolAddress((void**)&art1, g_art1);
    cudaGetSymbolAddress((void**)&tpl0, g_tpl0);
    cudaGetSymbolAddress((void**)&tpl1, g_tpl1);
    cudaGetSymbolAddress((void**)&a2,   g_a2);
    cudaGetSymbolAddress((void**)&t2,   g_t2);
    cudaGetSymbolAddress((void**)&rmax, g_rowmax);

    // 1. embedding gathers
    {
        int total_a = NB * AL * (DD / 4);
        gather_kernel<<<(total_a + 255) / 256, 256>>>(art_w, emb, art0, NB * AL);
        int total_t = NB * TL * (DD / 4);
        gather_kernel<<<(total_t + 255) / 256, 256>>>(tpl_w, emb, tpl0, NB * TL);
    }

    // 2. 10 residual conv-GLU blocks
    const int dils[10] = {1, 2, 4, 8, 16, 32, 32, 1, 1, 1};
    for (int i = 0; i < 10; ++i) {
        const float* w  = (i < 7) ? exp_w + (size_t)i * 3 * DD * TWO_D
                                  : ref_w + (size_t)(i - 7) * 3 * DD * TWO_D;
        const float* bb = (i < 7) ? exp_b + i * TWO_D
                                  : ref_b + (i - 7) * TWO_D;
        float* ain  = (i & 1) ? art1 : art0;
        float* aout = (i & 1) ? art0 : art1;
        float* tin  = (i & 1) ? tpl1 : tpl0;
        float* tout = (i & 1) ? tpl0 : tpl1;
        conv_glu_kernel<<<dim3(AL / 64, 4, NB), 256>>>(ain, aout, w, bb, AL, dils[i]);
        conv_glu_kernel<<<dim3(TL / 64, 4, NB), 256>>>(tin, tout, w, bb, TL, dils[i]);
    }

    // 3. squared norms
    norms_kernel<<<(NB * AL) / 8, 256>>>(art0, a2, NB * AL);
    norms_kernel<<<(NB * TL) / 8, 256>>>(tpl0, t2, NB * TL);

    // 4. fused distance + exp + mask + row-max
    rowmax_kernel<<<dim3(AL / 64, NB), 256>>>(art0, tpl0, a2, t2, amask, tmask, rmax);

    // 5. top-10 + MLP
    final_kernel<<<NB, 256>>>(rmax, ff1w, ff1b, ff2w, ff2b, out);
}

// round 3
// speedup vs baseline: 1.2566x; 1.0555x over previous
#include <cuda_runtime.h>
#include <math.h>

#define DD 256
#define TWO_D 512
#define NB 16
#define AL 1024
#define TL 512

// packed fp32x2 ops (sm_103a; ptxas won't auto-fuse — must be PTX)
#define FMA2(d, a, b, c) \
    asm("fma.rn.f32x2 %0, %1, %2, %3;" : "=l"(d) : "l"(a), "l"(b), "l"(c))
#define PACK2(d, x) \
    asm("mov.b64 %0, {%1, %1};" : "=l"(d) : "f"(x))
#define UNPACK2(lo, hi, v) \
    asm("mov.b64 {%0, %1}, %2;" : "=f"(lo), "=f"(hi) : "l"(v))

// ---------------- scratch (no allocations allowed) ----------------
__device__ float g_art0[NB * AL * DD];
__device__ float g_art1[NB * AL * DD];
__device__ float g_tpl0[NB * TL * DD];
__device__ float g_tpl1[NB * TL * DD];
__device__ float g_a2[NB * AL];
__device__ float g_t2[NB * TL];
__device__ float g_rowmax[NB * AL];

// ---------------- embedding gather ----------------
__global__ void gather_kernel(const int* __restrict__ idx,
                              const float* __restrict__ emb,
                              float* __restrict__ out, int nrows)
{
    int t = blockIdx.x * blockDim.x + threadIdx.x;
    int total = nrows * (DD / 4);
    if (t >= total) return;
    int row = t / (DD / 4);
    int c4  = t % (DD / 4);
    int w = idx[row];
    reinterpret_cast<float4*>(out)[(size_t)row * (DD / 4) + c4] =
        reinterpret_cast<const float4*>(emb)[(size_t)w * (DD / 4) + c4];
}

// ---------------- fused conv1d(K=3, dilated) + GLU + residual ----------------
// CTA tile: 128 positions x (64 a-cols + 64 g-cols). K=768 in 48 chunks of 16.
// Thread micro-tile: 8 positions x 4 cols (a and g) => 2 MAC per LDS byte.
__global__ __launch_bounds__(256) void conv_glu_kernel(
    const float* __restrict__ x, float* __restrict__ out,
    const float* __restrict__ w, const float* __restrict__ bias,
    int L, int dil)
{
    __shared__ __align__(16) float As[2][16][132];
    __shared__ __align__(16) float Ba[2][16][68];
    __shared__ __align__(16) float Bg[2][16][68];

    const int l0  = blockIdx.x * 128;
    const int co0 = blockIdx.y * 64;
    const int b   = blockIdx.z;
    const int tid = threadIdx.x;
    const int tx  = tid & 15;     // col quad: tx*4
    const int ty  = tid >> 4;     // position group: ty*8

    const float* xb = x + (size_t)b * L * DD;

    unsigned long long accA[8][2], accG[8][2];
#pragma unroll
    for (int i = 0; i < 8; i++)
#pragma unroll
        for (int j = 0; j < 2; j++) { accA[i][j] = 0ull; accG[i][j] = 0ull; }

    // A staging: am 0..127 position, akk 0 or 8 (two float4s)
    const int am  = tid >> 1;
    const int akk = (tid & 1) * 8;
    // B staging: bkk 0..15, bj 0..60
    const int bkk = tid >> 4;
    const int bj  = (tid & 15) * 4;

    float4 va0, va1, vba, vbg;

    // ---- prefetch chunk 0 (k=0, ci0=0) ----
    {
        const int p = l0 + am - dil;
        va0 = make_float4(0.f, 0.f, 0.f, 0.f);
        va1 = make_float4(0.f, 0.f, 0.f, 0.f);
        if (p >= 0 && p < L) {
            va0 = *reinterpret_cast<const float4*>(&xb[(size_t)p * DD + akk]);
            va1 = *reinterpret_cast<const float4*>(&xb[(size_t)p * DD + akk + 4]);
        }
        const float* wr = w + ((size_t)bkk) * TWO_D + co0 + bj;
        vba = *reinterpret_cast<const float4*>(wr);
        vbg = *reinterpret_cast<const float4*>(wr + DD);
    }
    As[0][akk + 0][am] = va0.x; As[0][akk + 1][am] = va0.y;
    As[0][akk + 2][am] = va0.z; As[0][akk + 3][am] = va0.w;
    As[0][akk + 4][am] = va1.x; As[0][akk + 5][am] = va1.y;
    As[0][akk + 6][am] = va1.z; As[0][akk + 7][am] = va1.w;
    *reinterpret_cast<float4*>(&Ba[0][bkk][bj]) = vba;
    *reinterpret_cast<float4*>(&Bg[0][bkk][bj]) = vbg;
    __syncthreads();

    for (int c = 0; c < 48; ++c) {
        const int st = c & 1;

        // prefetch chunk c+1 into registers
        if (c < 47) {
            const int cn  = c + 1;
            const int k   = cn >> 4;
            const int ci0 = (cn & 15) << 4;
            const int p = l0 + am + (k - 1) * dil;
            va0 = make_float4(0.f, 0.f, 0.f, 0.f);
            va1 = make_float4(0.f, 0.f, 0.f, 0.f);
            if (p >= 0 && p < L) {
                va0 = *reinterpret_cast<const float4*>(&xb[(size_t)p * DD + ci0 + akk]);
                va1 = *reinterpret_cast<const float4*>(&xb[(size_t)p * DD + ci0 + akk + 4]);
            }
            const float* wr = w + ((size_t)(k * DD + ci0 + bkk)) * TWO_D + co0 + bj;
            vba = *reinterpret_cast<const float4*>(wr);
            vbg = *reinterpret_cast<const float4*>(wr + DD);
        }

        // compute current chunk
#pragma unroll
        for (int kk = 0; kk < 16; ++kk) {
            float4 a4lo = *reinterpret_cast<const float4*>(&As[st][kk][ty * 8]);
            float4 a4hi = *reinterpret_cast<const float4*>(&As[st][kk][ty * 8 + 4]);
            ulonglong2 b2a = *reinterpret_cast<const ulonglong2*>(&Ba[st][kk][tx * 4]);
            ulonglong2 b2g = *reinterpret_cast<const ulonglong2*>(&Bg[st][kk][tx * 4]);
            unsigned long long d;
#define ROWSTEP(i, ax)                                       \
            PACK2(d, ax);                                    \
            FMA2(accA[i][0], d, b2a.x, accA[i][0]);          \
            FMA2(accA[i][1], d, b2a.y, accA[i][1]);          \
            FMA2(accG[i][0], d, b2g.x, accG[i][0]);          \
            FMA2(accG[i][1], d, b2g.y, accG[i][1]);
            ROWSTEP(0, a4lo.x)
            ROWSTEP(1, a4lo.y)
            ROWSTEP(2, a4lo.z)
            ROWSTEP(3, a4lo.w)
            ROWSTEP(4, a4hi.x)
            ROWSTEP(5, a4hi.y)
            ROWSTEP(6, a4hi.z)
            ROWSTEP(7, a4hi.w)
#undef ROWSTEP
        }

        // stage chunk c+1 into the other buffer
        if (c < 47) {
            const int sn = st ^ 1;
            As[sn][akk + 0][am] = va0.x; As[sn][akk + 1][am] = va0.y;
            As[sn][akk + 2][am] = va0.z; As[sn][akk + 3][am] = va0.w;
            As[sn][akk + 4][am] = va1.x; As[sn][akk + 5][am] = va1.y;
            As[sn][akk + 6][am] = va1.z; As[sn][akk + 7][am] = va1.w;
            *reinterpret_cast<float4*>(&Ba[sn][bkk][bj]) = vba;
            *reinterpret_cast<float4*>(&Bg[sn][bkk][bj]) = vbg;
        }
        __syncthreads();
    }

    // epilogue: bias, GLU, residual
    float ba0 = bias[co0 + tx * 4 + 0];
    float ba1 = bias[co0 + tx * 4 + 1];
    float ba2 = bias[co0 + tx * 4 + 2];
    float ba3 = bias[co0 + tx * 4 + 3];
    float bg0 = bias[co0 + tx * 4 + 0 + DD];
    float bg1 = bias[co0 + tx * 4 + 1 + DD];
    float bg2 = bias[co0 + tx * 4 + 2 + DD];
    float bg3 = bias[co0 + tx * 4 + 3 + DD];
#pragma unroll
    for (int i = 0; i < 8; i++) {
        int l = l0 + ty * 8 + i;
        float4 xv = *reinterpret_cast<const float4*>(&xb[(size_t)l * DD + co0 + tx * 4]);
        float a0, a1, a2v, a3, g0, g1, g2, g3;
        UNPACK2(a0, a1, accA[i][0]);
        UNPACK2(a2v, a3, accA[i][1]);
        UNPACK2(g0, g1, accG[i][0]);
        UNPACK2(g2, g3, accG[i][1]);
        float o0 = xv.x + (a0 + ba0) * (1.f / (1.f + expf(-(g0 + bg0))));
        float o1 = xv.y + (a1 + ba1) * (1.f / (1.f + expf(-(g1 + bg1))));
        float o2 = xv.z + (a2v + ba2) * (1.f / (1.f + expf(-(g2 + bg2))));
        float o3 = xv.w + (a3 + ba3) * (1.f / (1.f + expf(-(g3 + bg3))));
        *reinterpret_cast<float4*>(&out[((size_t)b * L + l) * DD + co0 + tx * 4]) =
            make_float4(o0, o1, o2, o3);
    }
}

// ---------------- row squared norms (one warp per row) ----------------
__global__ void norms_kernel(const float* __restrict__ x, float* __restrict__ out,
                             int nrows)
{
    int warp = (blockIdx.x * blockDim.x + threadIdx.x) >> 5;
    int lane = threadIdx.x & 31;
    if (warp >= nrows) return;
    const float* r = x + (size_t)warp * DD;
    float s = 0.f;
#pragma unroll
    for (int c = lane * 2; c < DD; c += 64) {
        float2 v = *reinterpret_cast<const float2*>(&r[c]);
        s += v.x * v.x + v.y * v.y;
    }
#pragma unroll
    for (int o = 16; o; o >>= 1) s += __shfl_xor_sync(0xffffffffu, s, o);
    if (lane == 0) out[warp] = s;
}

// ---------------- fused distance GEMM + exp + mask + row-max ----------------
__global__ __launch_bounds__(256) void rowmax_kernel(
    const float* __restrict__ art, const float* __restrict__ tpl,
    const float* __restrict__ a2, const float* __restrict__ t2,
    const float* __restrict__ amask, const float* __restrict__ tmask,
    float* __restrict__ rowmax)
{
    __shared__ __align__(16) float As[16][68];
    __shared__ __align__(16) float Bs[16][68];

    const int l0  = blockIdx.x * 64;
    const int b   = blockIdx.y;
    const int tid = threadIdx.x;
    const int tx  = tid & 15;
    const int ty  = tid >> 4;

    const float* ab = art + (size_t)b * AL * DD;
    const float* tb = tpl + (size_t)b * TL * DD;

    const int am  = tid >> 2;
    const int akk = (tid & 3) * 4;

    float rmax[4] = {0.f, 0.f, 0.f, 0.f};

    for (int t0 = 0; t0 < TL; t0 += 64) {
        float acc[4][4];
#pragma unroll
        for (int i = 0; i < 4; i++)
#pragma unroll
            for (int j = 0; j < 4; j++) acc[i][j] = 0.f;

        for (int c = 0; c < 16; ++c) {
            int d0 = c * 16;
            float4 va = *reinterpret_cast<const float4*>(&ab[(size_t)(l0 + am) * DD + d0 + akk]);
            float4 vb = *reinterpret_cast<const float4*>(&tb[(size_t)(t0 + am) * DD + d0 + akk]);
            __syncthreads();
            As[akk + 0][am] = va.x; As[akk + 1][am] = va.y;
            As[akk + 2][am] = va.z; As[akk + 3][am] = va.w;
            Bs[akk + 0][am] = vb.x; Bs[akk + 1][am] = vb.y;
            Bs[akk + 2][am] = vb.z; Bs[akk + 3][am] = vb.w;
            __syncthreads();
#pragma unroll
            for (int kk = 0; kk < 16; ++kk) {
                float4 a4 = *reinterpret_cast<const float4*>(&As[kk][ty * 4]);
                float4 b4 = *reinterpret_cast<const float4*>(&Bs[kk][tx * 4]);
                float av[4] = {a4.x, a4.y, a4.z, a4.w};
                float bv[4] = {b4.x, b4.y, b4.z, b4.w};
#pragma unroll
                for (int i = 0; i < 4; i++)
#pragma unroll
                    for (int j = 0; j < 4; j++)
                        acc[i][j] = fmaf(av[i], bv[j], acc[i][j]);
            }
        }

#pragma unroll
        for (int i = 0; i < 4; i++) {
            int l = l0 + ty * 4 + i;
            float av2 = a2[b * AL + l];
#pragma unroll
            for (int j = 0; j < 4; j++) {
                int t = t0 + tx * 4 + j;
                float dist = av2 + t2[b * TL + t] - 2.f * acc[i][j];
                dist = fmaxf(dist, 0.f);
                float s = expf(-dist) * tmask[b * TL + t];
                rmax[i] = fmaxf(rmax[i], s);
            }
        }
    }

#pragma unroll
    for (int i = 0; i < 4; i++) {
        float v = rmax[i];
#pragma unroll
        for (int o = 8; o; o >>= 1) v = fmaxf(v, __shfl_xor_sync(0xffffffffu, v, o));
        if (tx == 0) {
            int l = l0 + ty * 4 + i;
            rowmax[b * AL + l] = v * amask[b * AL + l];
        }
    }
}

// ---------------- top-10 (sorted desc) + 2-layer MLP ----------------
__global__ void final_kernel(const float* __restrict__ rowmax,
                             const float* __restrict__ ff1w, const float* __restrict__ ff1b,
                             const float* __restrict__ ff2w, const float* __restrict__ ff2b,
                             float* __restrict__ out)
{
    __shared__ float vals[AL];
    __shared__ float rv[256];
    __shared__ int   ri[256];
    __shared__ float topv[10];

    int b = blockIdx.x;
    int tid = threadIdx.x;
    for (int i = tid; i < AL; i += 256) vals[i] = rowmax[b * AL + i];
    __syncthreads();

    for (int it = 0; it < 10; ++it) {
        float bv = -1.f; int bi = 0;
        for (int i = tid; i < AL; i += 256) {
            float v = vals[i];
            if (v > bv) { bv = v; bi = i; }
        }
        rv[tid] = bv; ri[tid] = bi;
        __syncthreads();
        for (int s = 128; s; s >>= 1) {
            if (tid < s && rv[tid + s] > rv[tid]) { rv[tid] = rv[tid + s]; ri[tid] = ri[tid + s]; }
            __syncthreads();
        }
        if (tid == 0) { topv[it] = rv[0]; vals[ri[0]] = -2.f; }
        __syncthreads();
    }

    if (tid == 0) {
        float o = ff2b[0];
#pragma unroll
        for (int j = 0; j < 10; j++) {
            float h = ff1b[j];
#pragma unroll
            for (int i = 0; i < 10; i++) h += topv[i] * ff1w[i * 10 + j];
            h = fmaxf(h, 0.f);
            o += h * ff2w[j];
        }
        out[b] = o;
    }
}

// ---------------- launcher ----------------
extern "C" void kernel_launch(void* const* d_in, const int* in_sizes, int n_in,
                              void* d_out, int out_size)
{
    const int*   art_w = (const int*)d_in[0];
    const int*   tpl_w = (const int*)d_in[2];
    const float* amask = (const float*)d_in[4];
    const float* tmask = (const float*)d_in[5];
    const float* emb   = (const float*)d_in[6];
    const float* exp_w = (const float*)d_in[7];
    const float* exp_b = (const float*)d_in[8];
    const float* ref_w = (const float*)d_in[9];
    const float* ref_b = (const float*)d_in[10];
    const float* ff1w  = (const float*)d_in[11];
    const float* ff1b  = (const float*)d_in[12];
    const float* ff2w  = (const float*)d_in[13];
    const float* ff2b  = (const float*)d_in[14];
    float* out = (float*)d_out;

    float *art0, *art1, *tpl0, *tpl1, *a2, *t2, *rmax;
    cudaGetSymbolAddress((void**)&art0, g_art0);
    cudaGetSymbolAddress((void**)&art1, g_art1);
    cudaGetSymbolAddress((void**)&tpl0, g_tpl0);
    cudaGetSymbolAddress((void**)&tpl1, g_tpl1);
    cudaGetSymbolAddress((void**)&a2,   g_a2);
    cudaGetSymbolAddress((void**)&t2,   g_t2);
    cudaGetSymbolAddress((void**)&rmax, g_rowmax);

    // 1. embedding gathers
    {
        int total_a = NB * AL * (DD / 4);
        gather_kernel<<<(total_a + 255) / 256, 256>>>(art_w, emb, art0, NB * AL);
        int total_t = NB * TL * (DD / 4);
        gather_kernel<<<(total_t + 255) / 256, 256>>>(tpl_w, emb, tpl0, NB * TL);
    }

    // 2. 10 residual conv-GLU blocks
    const int dils[10] = {1, 2, 4, 8, 16, 32, 32, 1, 1, 1};
    for (int i = 0; i < 10; ++i) {
        const float* w  = (i < 7) ? exp_w + (size_t)i * 3 * DD * TWO_D
                                  : ref_w + (size_t)(i - 7) * 3 * DD * TWO_D;
        const float* bb = (i < 7) ? exp_b + i * TWO_D
                                  : ref_b + (i - 7) * TWO_D;
        float* ain  = (i & 1) ? art1 : art0;
        float* aout = (i & 1) ? art0 : art1;
        float* tin  = (i & 1) ? tpl1 : tpl0;
        float* tout = (i & 1) ? tpl0 : tpl1;
        conv_glu_kernel<<<dim3(AL / 128, 4, NB), 256>>>(ain, aout, w, bb, AL, dils[i]);
        conv_glu_kernel<<<dim3(TL / 128, 4, NB), 256>>>(tin, tout, w, bb, TL, dils[i]);
    }

    // 3. squared norms
    norms_kernel<<<(NB * AL) / 8, 256>>>(art0, a2, NB * AL);
    norms_kernel<<<(NB * TL) / 8, 256>>>(tpl0, t2, NB * TL);

    // 4. fused distance + exp + mask + row-max
    rowmax_kernel<<<dim3(AL / 64, NB), 256>>>(art0, tpl0, a2, t2, amask, tmask, rmax);

    // 5. top-10 + MLP
    final_kernel<<<NB, 256>>>(rmax, ff1w, ff1b, ff2w, ff2b, out);
}